// round 9
// baseline (speedup 1.0000x reference)
#include <cuda_runtime.h>
#include <cstdint>

#define BATCH 16384
#define NPTS  4096
#define LAT   64
#define KC    1024

// ---------------- scratch (static device allocations) ----------------
__device__ float g_h1[BATCH * 512];
__device__ float g_h2[BATCH * 256];
__device__ float g_z [BATCH * LAT];
__device__ float g_zq[BATCH * LAT];      // holds zq_st (decoder input)
__device__ float g_zc[BATCH * KC];       // (2z) @ cb^T
__device__ float g_cbT[LAT * KC];        // codebook transposed [64][1024]
__device__ float g_zz[BATCH];
__device__ float g_cc[KC];
__device__ int   g_idx[BATCH];
__device__ float g_rpart[8192];          // (4096/64)*(16384/128)
__device__ float g_vpart[2048];          // BATCH/8

// ================================================================
// PART 1: bit-exact fp32 path (matches XLA:CPU / Eigen semantics)
// ================================================================

// Sequential-k fp32 FMA-chain GEMM: C[m,n] = chain_{k=0..K-1} fma(A[m,k],B[k,n])
// (single accumulator per output, ascending k — Eigen gebp order).
// Optional: out = max(fl(acc + bias[n]), 0)
template<bool RELU, bool HAS_BIAS, bool DOUBLE_A>
__global__ __launch_bounds__(256)
void seqk_gemm(const float* __restrict__ A, const float* __restrict__ B,
               const float* __restrict__ bias, float* __restrict__ C,
               int M, int N, int K)
{
    __shared__ float As[64 * 68];   // transposed [k][m], pad 68 keeps float4 alignment
    __shared__ float Bs[64 * 64];   // [k][n]

    const int tid  = threadIdx.x;
    const int mBlk = blockIdx.y * 64;
    const int nBlk = blockIdx.x * 64;

    const int m0 = (tid >> 4) * 4;    // 0..60
    const int n0 = (tid & 15) * 4;    // 0..60

    float acc[4][4];
    #pragma unroll
    for (int i = 0; i < 4; i++)
        #pragma unroll
        for (int j = 0; j < 4; j++) acc[i][j] = 0.f;

    const int la_m = tid >> 2;          // 0..63 (A row / B k-row)
    const int la_k = (tid & 3) * 16;    // 0,16,32,48

    for (int k0 = 0; k0 < K; k0 += 64) {
        // stage A (64 m x 64 k) transposed into As[k][m]
        #pragma unroll
        for (int j = 0; j < 4; j++) {
            float4 v = *(const float4*)(A + (size_t)(mBlk + la_m) * K + (k0 + la_k + 4 * j));
            if (DOUBLE_A) { v.x *= 2.f; v.y *= 2.f; v.z *= 2.f; v.w *= 2.f; }  // exact
            As[(la_k + 4 * j + 0) * 68 + la_m] = v.x;
            As[(la_k + 4 * j + 1) * 68 + la_m] = v.y;
            As[(la_k + 4 * j + 2) * 68 + la_m] = v.z;
            As[(la_k + 4 * j + 3) * 68 + la_m] = v.w;
        }
        // stage B (64 k x 64 n)
        #pragma unroll
        for (int j = 0; j < 4; j++) {
            float4 v = *(const float4*)(B + (size_t)(k0 + la_m) * N + (nBlk + la_k + 4 * j));
            *(float4*)&Bs[la_m * 64 + la_k + 4 * j] = v;
        }
        __syncthreads();

        #pragma unroll 8
        for (int k = 0; k < 64; k++) {
            float4 av = *(const float4*)&As[k * 68 + m0];
            float4 bv = *(const float4*)&Bs[k * 64 + n0];
            float a[4] = {av.x, av.y, av.z, av.w};
            float b[4] = {bv.x, bv.y, bv.z, bv.w};
            #pragma unroll
            for (int i = 0; i < 4; i++)
                #pragma unroll
                for (int j = 0; j < 4; j++)
                    acc[i][j] = __fmaf_rn(a[i], b[j], acc[i][j]);   // forced fp32 FMA chain
        }
        __syncthreads();
    }

    #pragma unroll
    for (int i = 0; i < 4; i++) {
        float4 o;
        float r[4];
        #pragma unroll
        for (int j = 0; j < 4; j++) {
            float v = acc[i][j];
            if (HAS_BIAS) v = __fadd_rn(v, bias[nBlk + n0 + j]);   // fl(acc + b)
            if (RELU)     v = fmaxf(v, 0.f);                        // exact
            r[j] = v;
        }
        o.x = r[0]; o.y = r[1]; o.z = r[2]; o.w = r[3];
        *(float4*)(C + (size_t)(mBlk + m0 + i) * N + (nBlk + n0)) = o;
    }
}

// codebook transpose (exact copy)
__global__ void cbT_kernel(const float* __restrict__ cb) {
    int i = blockIdx.x * 256 + threadIdx.x;   // i over 1024*64
    int c = i >> 6, l = i & 63;
    g_cbT[l * KC + c] = cb[c * LAT + l];
}

// zz[m] = sequential ascending sum of fl(z_i * z_i)
__global__ void zz_kernel(const float* __restrict__ z) {
    int row = blockIdx.x * 256 + threadIdx.x;
    const float* zr = z + (size_t)row * LAT;
    float acc = 0.f;
    for (int i = 0; i < LAT; i++)
        acc = __fadd_rn(acc, __fmul_rn(zr[i], zr[i]));
    g_zz[row] = acc;
}

// cc[c] = sequential ascending sum of fl(c_i * c_i)
__global__ void cc_kernel(const float* __restrict__ cb) {
    int c = blockIdx.x * 256 + threadIdx.x;
    if (c < KC) {
        const float* cr = cb + (size_t)c * LAT;
        float acc = 0.f;
        for (int i = 0; i < LAT; i++)
            acc = __fadd_rn(acc, __fmul_rn(cr[i], cr[i]));
        g_cc[c] = acc;
    }
}

// d = fl(fl(zz - m2) + cc)  (m2 = (2z)@cbT, bit-equal to fl(2*(z@cbT)));
// argmin with first-index tie-break (== jnp.argmin).
__global__ __launch_bounds__(256)
void argmin_kernel() {
    const int tid  = threadIdx.x;
    const int lane = tid & 31;
    const int wrp  = tid >> 5;
    const int row  = blockIdx.x * 8 + wrp;

    const float zz = g_zz[row];
    const float* zcr = g_zc + (size_t)row * KC;

    float best = 3.402823466e38f;
    int bi = KC;
    for (int j = 0; j < KC / 32; j++) {
        int c = j * 32 + lane;                     // coalesced
        float d = __fadd_rn(__fsub_rn(zz, zcr[c]), g_cc[c]);
        if (d < best || (d == best && c < bi)) { best = d; bi = c; }
    }
    #pragma unroll
    for (int off = 16; off > 0; off >>= 1) {
        float ov = __shfl_down_sync(0xFFFFFFFFu, best, off);
        int   oi = __shfl_down_sync(0xFFFFFFFFu, bi,   off);
        if (ov < best || (ov == best && oi < bi)) { best = ov; bi = oi; }
    }
    if (lane == 0) g_idx[row] = bi;
}

// zq_st = fl(z + fl(zq - z)); vq partial = sum fl(zq - z)^2 per block
__global__ __launch_bounds__(256)
void zq_kernel(const float* __restrict__ z, const float* __restrict__ cb) {
    const int tid  = threadIdx.x;
    const int lane = tid & 31;
    const int wrp  = tid >> 5;
    const int row  = blockIdx.x * 8 + wrp;
    const int bi   = g_idx[row];

    float vs = 0.f;
    #pragma unroll
    for (int h = 0; h < 2; h++) {
        int i = h * 32 + lane;
        float zv = z[(size_t)row * LAT + i];
        float cv = cb[(size_t)bi * LAT + i];
        float df = __fsub_rn(cv, zv);                 // fl(zq - z)
        g_zq[(size_t)row * LAT + i] = __fadd_rn(zv, df);  // straight-through value
        vs = __fmaf_rn(df, df, vs);
    }
    #pragma unroll
    for (int off = 16; off > 0; off >>= 1)
        vs += __shfl_down_sync(0xFFFFFFFFu, vs, off);

    __shared__ float sv[8];
    if (lane == 0) sv[wrp] = vs;
    __syncthreads();
    if (tid == 0) {
        float s = 0.f;
        #pragma unroll
        for (int w = 0; w < 8; w++) s += sv[w];       // deterministic order
        g_vpart[blockIdx.x] = s;
    }
}

// ================================================================
// PART 2: fast tf32x3 decoder (tolerance-checked path)
// ================================================================
__device__ __forceinline__ void mma_tf32(float* c, const uint32_t* a, const uint32_t* b) {
    asm volatile(
        "mma.sync.aligned.m16n8k8.row.col.f32.tf32.tf32.f32 "
        "{%0,%1,%2,%3},{%4,%5,%6,%7},{%8,%9},{%0,%1,%2,%3};\n"
        : "+f"(c[0]), "+f"(c[1]), "+f"(c[2]), "+f"(c[3])
        : "r"(a[0]), "r"(a[1]), "r"(a[2]), "r"(a[3]),
          "r"(b[0]), "r"(b[1]));
}
__device__ __forceinline__ float tf32_hi(float x) {
    return __uint_as_float(__float_as_uint(x) & 0xFFFFE000u);
}

constexpr int BM = 128, BN = 64, BK = 16;
constexpr int SA = 20, SB = 72;

template<bool RELU, bool FINAL>
__global__ __launch_bounds__(256)
void gemm_x3(const float* __restrict__ A, const float* __restrict__ W,
             const float* __restrict__ bias, float* __restrict__ C,
             int M, int N, int K,
             const float* __restrict__ xref, float* __restrict__ part)
{
    __shared__ float As[2][BM * SA];
    __shared__ float Bs[2][BK * SB];

    const int tid  = threadIdx.x;
    const int lane = tid & 31;
    const int warp = tid >> 5;
    const int gid  = lane >> 2;
    const int tig  = lane & 3;
    const int wm   = warp & 3;
    const int wn   = warp >> 2;
    const int rowBlk = blockIdx.y * BM;
    const int colBlk = blockIdx.x * BN;

    float acc[2][4][4];
    #pragma unroll
    for (int i = 0; i < 2; i++)
        #pragma unroll
        for (int j = 0; j < 4; j++)
            #pragma unroll
            for (int q = 0; q < 4; q++) acc[i][j][q] = 0.f;

    for (int k0 = 0; k0 < K; k0 += BK) {
        #pragma unroll
        for (int i = 0; i < 2; i++) {
            int idx = tid + i * 256;
            int r  = idx >> 2;
            int kc = (idx & 3) * 4;
            float4 v = *(const float4*)(A + (size_t)(rowBlk + r) * K + (k0 + kc));
            float4 h, l;
            h.x = tf32_hi(v.x); h.y = tf32_hi(v.y); h.z = tf32_hi(v.z); h.w = tf32_hi(v.w);
            l.x = v.x - h.x;    l.y = v.y - h.y;    l.z = v.z - h.z;    l.w = v.w - h.w;
            *(float4*)&As[0][r * SA + kc] = h;
            *(float4*)&As[1][r * SA + kc] = l;
        }
        {
            int kr = tid >> 4;
            int nc = (tid & 15) * 4;
            float4 v = *(const float4*)(W + (size_t)(k0 + kr) * N + (colBlk + nc));
            float4 h, l;
            h.x = tf32_hi(v.x); h.y = tf32_hi(v.y); h.z = tf32_hi(v.z); h.w = tf32_hi(v.w);
            l.x = v.x - h.x;    l.y = v.y - h.y;    l.z = v.z - h.z;    l.w = v.w - h.w;
            *(float4*)&Bs[0][kr * SB + nc] = h;
            *(float4*)&Bs[1][kr * SB + nc] = l;
        }
        __syncthreads();

        #pragma unroll
        for (int ks = 0; ks < BK / 8; ks++) {
            uint32_t a[2][4], b[4][2], al[2][4], bl[4][2];
            #pragma unroll
            for (int mt = 0; mt < 2; mt++) {
                int rb = wm * 32 + mt * 16 + gid;
                int cc2 = ks * 8 + tig;
                a[mt][0]  = __float_as_uint(As[0][rb * SA + cc2]);
                a[mt][1]  = __float_as_uint(As[0][(rb + 8) * SA + cc2]);
                a[mt][2]  = __float_as_uint(As[0][rb * SA + cc2 + 4]);
                a[mt][3]  = __float_as_uint(As[0][(rb + 8) * SA + cc2 + 4]);
                al[mt][0] = __float_as_uint(As[1][rb * SA + cc2]);
                al[mt][1] = __float_as_uint(As[1][(rb + 8) * SA + cc2]);
                al[mt][2] = __float_as_uint(As[1][rb * SA + cc2 + 4]);
                al[mt][3] = __float_as_uint(As[1][(rb + 8) * SA + cc2 + 4]);
            }
            #pragma unroll
            for (int nt = 0; nt < 4; nt++) {
                int nn = wn * 32 + nt * 8 + gid;
                int kk = ks * 8 + tig;
                b[nt][0]  = __float_as_uint(Bs[0][kk * SB + nn]);
                b[nt][1]  = __float_as_uint(Bs[0][(kk + 4) * SB + nn]);
                bl[nt][0] = __float_as_uint(Bs[1][kk * SB + nn]);
                bl[nt][1] = __float_as_uint(Bs[1][(kk + 4) * SB + nn]);
            }
            #pragma unroll
            for (int mt = 0; mt < 2; mt++)
                #pragma unroll
                for (int nt = 0; nt < 4; nt++) {
                    mma_tf32(acc[mt][nt], a[mt], b[nt]);
                    mma_tf32(acc[mt][nt], al[mt], b[nt]);
                    mma_tf32(acc[mt][nt], a[mt], bl[nt]);
                }
        }
        __syncthreads();
    }

    float lsum = 0.f;
    #pragma unroll
    for (int mt = 0; mt < 2; mt++) {
        #pragma unroll
        for (int nt = 0; nt < 4; nt++) {
            int col = colBlk + wn * 32 + nt * 8 + tig * 2;
            float b0 = bias[col], b1 = bias[col + 1];
            #pragma unroll
            for (int h = 0; h < 2; h++) {
                int row = rowBlk + wm * 32 + mt * 16 + gid + h * 8;
                float v0 = acc[mt][nt][h * 2 + 0] + b0;
                float v1 = acc[mt][nt][h * 2 + 1] + b1;
                if (RELU) { v0 = fmaxf(v0, 0.f); v1 = fmaxf(v1, 0.f); }
                *(float2*)(C + (size_t)row * N + col) = make_float2(v0, v1);
                if (FINAL) {
                    float x0 = xref[(size_t)row * N + col];
                    float x1 = xref[(size_t)row * N + col + 1];
                    float d0 = v0 - x0, d1 = v1 - x1;
                    lsum += d0 * d0 + d1 * d1;
                }
            }
        }
    }
    if (FINAL) {
        __shared__ float red[256];
        red[tid] = lsum;
        __syncthreads();
        #pragma unroll
        for (int s = 128; s > 0; s >>= 1) {
            if (tid < s) red[tid] += red[tid + s];
            __syncthreads();
        }
        if (tid == 0) part[blockIdx.y * gridDim.x + blockIdx.x] = red[0];
    }
}

// ---------------- tail outputs ----------------
__global__ void idxf_kernel(float* __restrict__ out) {
    int i = blockIdx.x * 256 + threadIdx.x;
    if (i < BATCH) out[i] = (float)g_idx[i];
}

__global__ __launch_bounds__(256)
void finalize_kernel(float* __restrict__ out) {
    __shared__ double sd[256];
    int tid = threadIdx.x;
    double s = 0.0;
    for (int i = tid; i < 8192; i += 256) s += (double)g_rpart[i];
    sd[tid] = s;
    __syncthreads();
    for (int st = 128; st > 0; st >>= 1) {
        if (tid < st) sd[tid] += sd[tid + st];
        __syncthreads();
    }
    double recon_sum = sd[0];
    __syncthreads();
    s = 0.0;
    for (int i = tid; i < 2048; i += 256) s += (double)g_vpart[i];
    sd[tid] = s;
    __syncthreads();
    for (int st = 128; st > 0; st >>= 1) {
        if (tid < st) sd[tid] += sd[tid + st];
        __syncthreads();
    }
    if (tid == 0) {
        double recon = recon_sum / ((double)BATCH * (double)NPTS);
        double vq    = 1.25 * sd[0] / ((double)BATCH * (double)LAT);
        out[0] = (float)(recon + vq);
        out[1] = (float)recon;
        out[2] = (float)vq;
    }
}

// ---------------- launch ----------------
extern "C" void kernel_launch(void* const* d_in, const int* in_sizes, int n_in,
                              void* d_out, int out_size)
{
    const float* x   = (const float*)d_in[0];
    const float* ew1 = (const float*)d_in[1];
    const float* eb1 = (const float*)d_in[2];
    const float* ew2 = (const float*)d_in[3];
    const float* eb2 = (const float*)d_in[4];
    const float* ew3 = (const float*)d_in[5];
    const float* eb3 = (const float*)d_in[6];
    const float* cb  = (const float*)d_in[7];
    const float* dw1 = (const float*)d_in[8];
    const float* db1 = (const float*)d_in[9];
    const float* dw2 = (const float*)d_in[10];
    const float* db2 = (const float*)d_in[11];
    const float* dw3 = (const float*)d_in[12];
    const float* db3 = (const float*)d_in[13];
    float* out = (float*)d_out;

    float *h1, *h2, *z, *zq, *zc, *cbT, *rpart;
    cudaGetSymbolAddress((void**)&h1, g_h1);
    cudaGetSymbolAddress((void**)&h2, g_h2);
    cudaGetSymbolAddress((void**)&z,  g_z);
    cudaGetSymbolAddress((void**)&zq, g_zq);
    cudaGetSymbolAddress((void**)&zc, g_zc);
    cudaGetSymbolAddress((void**)&cbT, g_cbT);
    cudaGetSymbolAddress((void**)&rpart, g_rpart);

    dim3 blk(256);

    // ---- encoder: bit-exact sequential-k fp32 (Eigen-order) ----
    seqk_gemm<true,  true,  false><<<dim3(512 / 64,  BATCH / 64), blk>>>(x,  ew1, eb1, h1, BATCH, 512, NPTS);
    seqk_gemm<true,  true,  false><<<dim3(256 / 64,  BATCH / 64), blk>>>(h1, ew2, eb2, h2, BATCH, 256, 512);
    seqk_gemm<false, true,  false><<<dim3(64 / 64,   BATCH / 64), blk>>>(h2, ew3, eb3, z,  BATCH, 64,  256);

    // ---- VQ: bit-exact d + first-index argmin ----
    cbT_kernel<<<(KC * LAT) / 256, blk>>>(cb);
    cc_kernel<<<KC / 256, blk>>>(cb);
    zz_kernel<<<BATCH / 256, blk>>>(z);
    seqk_gemm<false, false, true ><<<dim3(KC / 64, BATCH / 64), blk>>>(z, cbT, nullptr, zc, BATCH, KC, LAT);
    argmin_kernel<<<BATCH / 8, blk>>>();
    zq_kernel<<<BATCH / 8, blk>>>(z, cb);

    // ---- decoder: fast tf32x3 (tolerance path) ----
    gemm_x3<true,  false><<<dim3(256 / BN,  BATCH / BM), blk>>>(zq, dw1, db1, h2, BATCH, 256,  LAT, nullptr, nullptr);
    gemm_x3<true,  false><<<dim3(512 / BN,  BATCH / BM), blk>>>(h2, dw2, db2, h1, BATCH, 512,  256, nullptr, nullptr);
    gemm_x3<false, true ><<<dim3(NPTS / BN, BATCH / BM), blk>>>(h1, dw3, db3, out, BATCH, NPTS, 512, x, rpart);

    // ---- tail outputs ----
    idxf_kernel<<<BATCH / 256, blk>>>(out + (size_t)BATCH * NPTS);
    finalize_kernel<<<1, blk>>>(out + (size_t)BATCH * NPTS + BATCH);
}

// round 10
// speedup vs baseline: 1.1810x; 1.1810x over previous
#include <cuda_runtime.h>
#include <cstdint>

#define BATCH 16384
#define NPTS  4096
#define LAT   64
#define KC    1024

// ---------------- scratch (static device allocations) ----------------
__device__ float g_h1[BATCH * 512];
__device__ float g_h2[BATCH * 256];
__device__ float g_z [BATCH * LAT];
__device__ float g_zq[BATCH * LAT];      // holds zq_st (decoder input)
__device__ float g_zc[BATCH * KC];       // (2z) @ cb^T
__device__ float g_cbT[LAT * KC];        // codebook transposed [64][1024]
__device__ float g_zz[BATCH];
__device__ float g_cc[KC];
__device__ int   g_idx[BATCH];
__device__ float g_rpart[8192];          // (4096/64)*(16384/128)
__device__ float g_vpart[2048];          // BATCH/8

// ---------------- packed f32x2 helpers (bit-exact per-lane IEEE FMA) ----------------
__device__ __forceinline__ void fma2(unsigned long long& acc, unsigned long long a, unsigned long long b) {
    asm("fma.rn.f32x2 %0, %1, %2, %0;" : "+l"(acc) : "l"(a), "l"(b));
}
__device__ __forceinline__ unsigned long long pack2(float lo, float hi) {
    unsigned long long r;
    asm("mov.b64 %0, {%1,%2};" : "=l"(r) : "f"(lo), "f"(hi));
    return r;
}
__device__ __forceinline__ unsigned long long add2(unsigned long long a, unsigned long long b) {
    unsigned long long r;
    asm("add.rn.f32x2 %0, %1, %2;" : "=l"(r) : "l"(a), "l"(b));
    return r;
}
__device__ __forceinline__ float2 unpack2(unsigned long long v) {
    float2 f;
    asm("mov.b64 {%0,%1}, %2;" : "=f"(f.x), "=f"(f.y) : "l"(v));
    return f;
}

// ================================================================
// PART 1: bit-exact fp32 path (matches XLA:CPU / Eigen semantics)
// Each output = single fp32 FMA chain, ascending k.
// ================================================================

// ---- v2: FFMA2-packed 128x128 tile, 8x8 per thread, BK=32 ----
template<bool RELU, bool HAS_BIAS, bool DOUBLE_A>
__global__ __launch_bounds__(256, 2)
void seqk_gemm2(const float* __restrict__ A, const float* __restrict__ B,
                const float* __restrict__ bias, float* __restrict__ C,
                int M, int N, int K)
{
    __shared__ float As[32][128];   // [k][m] transposed
    __shared__ float Bs[32][128];   // [k][n]

    const int tid  = threadIdx.x;
    const int mBlk = blockIdx.y * 128;
    const int nBlk = blockIdx.x * 128;

    const int tm = tid >> 4;          // 0..15
    const int tn = tid & 15;          // 0..15
    const int m0 = tm * 8;
    const int n0 = tn * 8;

    // acc[mp][j]: packed rows (m0+2mp, m0+2mp+1), col n0+j
    unsigned long long acc[4][8];
    #pragma unroll
    for (int i = 0; i < 4; i++)
        #pragma unroll
        for (int j = 0; j < 8; j++) acc[i][j] = 0ull;

    // staging assignments
    const int a_row = tid & 127;        // A row within tile
    const int a_kq  = (tid >> 7) * 16;  // k sub-offset 0 or 16
    const int b_k   = tid >> 3;         // 0..31
    const int b_n   = (tid & 7) * 4;    // base col (float) within q-groups of 32

    for (int k0 = 0; k0 < K; k0 += 32) {
        // stage A (128 m x 32 k), transposed into As[k][m]
        #pragma unroll
        for (int j = 0; j < 4; j++) {
            float4 v = *(const float4*)(A + (size_t)(mBlk + a_row) * K + (k0 + a_kq + 4 * j));
            if (DOUBLE_A) { v.x *= 2.f; v.y *= 2.f; v.z *= 2.f; v.w *= 2.f; }  // exact (power of 2)
            As[a_kq + 4 * j + 0][a_row] = v.x;
            As[a_kq + 4 * j + 1][a_row] = v.y;
            As[a_kq + 4 * j + 2][a_row] = v.z;
            As[a_kq + 4 * j + 3][a_row] = v.w;
        }
        // stage B (32 k x 128 n)
        #pragma unroll
        for (int q = 0; q < 4; q++) {
            float4 v = *(const float4*)(B + (size_t)(k0 + b_k) * N + (nBlk + b_n + q * 32));
            *(float4*)&Bs[b_k][b_n + q * 32] = v;
        }
        __syncthreads();

        #pragma unroll 8
        for (int kk = 0; kk < 32; kk++) {
            float4 av0 = *(const float4*)&As[kk][m0];
            float4 av1 = *(const float4*)&As[kk][m0 + 4];
            float4 bv0 = *(const float4*)&Bs[kk][n0];
            float4 bv1 = *(const float4*)&Bs[kk][n0 + 4];
            unsigned long long ap[4], bd[8];
            ap[0] = pack2(av0.x, av0.y);
            ap[1] = pack2(av0.z, av0.w);
            ap[2] = pack2(av1.x, av1.y);
            ap[3] = pack2(av1.z, av1.w);
            bd[0] = pack2(bv0.x, bv0.x);
            bd[1] = pack2(bv0.y, bv0.y);
            bd[2] = pack2(bv0.z, bv0.z);
            bd[3] = pack2(bv0.w, bv0.w);
            bd[4] = pack2(bv1.x, bv1.x);
            bd[5] = pack2(bv1.y, bv1.y);
            bd[6] = pack2(bv1.z, bv1.z);
            bd[7] = pack2(bv1.w, bv1.w);
            #pragma unroll
            for (int mp = 0; mp < 4; mp++)
                #pragma unroll
                for (int j = 0; j < 8; j++)
                    fma2(acc[mp][j], ap[mp], bd[j]);   // 2 exact fp32 FMA chains per op
        }
        __syncthreads();
    }

    // epilogue
    float bb[8];
    #pragma unroll
    for (int j = 0; j < 8; j++) bb[j] = HAS_BIAS ? bias[nBlk + n0 + j] : 0.f;

    #pragma unroll
    for (int mp = 0; mp < 4; mp++) {
        float r0[8], r1[8];
        #pragma unroll
        for (int j = 0; j < 8; j++) {
            float2 v = unpack2(acc[mp][j]);
            float v0 = v.x, v1 = v.y;
            if (HAS_BIAS) { v0 = __fadd_rn(v0, bb[j]); v1 = __fadd_rn(v1, bb[j]); }
            if (RELU)     { v0 = fmaxf(v0, 0.f);       v1 = fmaxf(v1, 0.f); }
            r0[j] = v0; r1[j] = v1;
        }
        int row0 = mBlk + m0 + 2 * mp;
        *(float4*)(C + (size_t)row0 * N + nBlk + n0)           = make_float4(r0[0], r0[1], r0[2], r0[3]);
        *(float4*)(C + (size_t)row0 * N + nBlk + n0 + 4)       = make_float4(r0[4], r0[5], r0[6], r0[7]);
        *(float4*)(C + (size_t)(row0 + 1) * N + nBlk + n0)     = make_float4(r1[0], r1[1], r1[2], r1[3]);
        *(float4*)(C + (size_t)(row0 + 1) * N + nBlk + n0 + 4) = make_float4(r1[4], r1[5], r1[6], r1[7]);
    }
}

// ---- v1: 64x64 tile (kept only for enc3, N=64) ----
template<bool RELU, bool HAS_BIAS, bool DOUBLE_A>
__global__ __launch_bounds__(256)
void seqk_gemm(const float* __restrict__ A, const float* __restrict__ B,
               const float* __restrict__ bias, float* __restrict__ C,
               int M, int N, int K)
{
    __shared__ float As[64 * 68];
    __shared__ float Bs[64 * 64];

    const int tid  = threadIdx.x;
    const int mBlk = blockIdx.y * 64;
    const int nBlk = blockIdx.x * 64;

    const int m0 = (tid >> 4) * 4;
    const int n0 = (tid & 15) * 4;

    float acc[4][4];
    #pragma unroll
    for (int i = 0; i < 4; i++)
        #pragma unroll
        for (int j = 0; j < 4; j++) acc[i][j] = 0.f;

    const int la_m = tid >> 2;
    const int la_k = (tid & 3) * 16;

    for (int k0 = 0; k0 < K; k0 += 64) {
        #pragma unroll
        for (int j = 0; j < 4; j++) {
            float4 v = *(const float4*)(A + (size_t)(mBlk + la_m) * K + (k0 + la_k + 4 * j));
            if (DOUBLE_A) { v.x *= 2.f; v.y *= 2.f; v.z *= 2.f; v.w *= 2.f; }
            As[(la_k + 4 * j + 0) * 68 + la_m] = v.x;
            As[(la_k + 4 * j + 1) * 68 + la_m] = v.y;
            As[(la_k + 4 * j + 2) * 68 + la_m] = v.z;
            As[(la_k + 4 * j + 3) * 68 + la_m] = v.w;
        }
        #pragma unroll
        for (int j = 0; j < 4; j++) {
            float4 v = *(const float4*)(B + (size_t)(k0 + la_m) * N + (nBlk + la_k + 4 * j));
            *(float4*)&Bs[la_m * 64 + la_k + 4 * j] = v;
        }
        __syncthreads();

        #pragma unroll 8
        for (int k = 0; k < 64; k++) {
            float4 av = *(const float4*)&As[k * 68 + m0];
            float4 bv = *(const float4*)&Bs[k * 64 + n0];
            float a[4] = {av.x, av.y, av.z, av.w};
            float b[4] = {bv.x, bv.y, bv.z, bv.w};
            #pragma unroll
            for (int i = 0; i < 4; i++)
                #pragma unroll
                for (int j = 0; j < 4; j++)
                    acc[i][j] = __fmaf_rn(a[i], b[j], acc[i][j]);
        }
        __syncthreads();
    }

    #pragma unroll
    for (int i = 0; i < 4; i++) {
        float4 o;
        float r[4];
        #pragma unroll
        for (int j = 0; j < 4; j++) {
            float v = acc[i][j];
            if (HAS_BIAS) v = __fadd_rn(v, bias[nBlk + n0 + j]);
            if (RELU)     v = fmaxf(v, 0.f);
            r[j] = v;
        }
        o.x = r[0]; o.y = r[1]; o.z = r[2]; o.w = r[3];
        *(float4*)(C + (size_t)(mBlk + m0 + i) * N + (nBlk + n0)) = o;
    }
}

// codebook transpose (exact copy)
__global__ void cbT_kernel(const float* __restrict__ cb) {
    int i = blockIdx.x * 256 + threadIdx.x;
    int c = i >> 6, l = i & 63;
    g_cbT[l * KC + c] = cb[c * LAT + l];
}

// zz[m] = sequential ascending sum of fl(z_i * z_i)
__global__ void zz_kernel(const float* __restrict__ z) {
    int row = blockIdx.x * 256 + threadIdx.x;
    const float* zr = z + (size_t)row * LAT;
    float acc = 0.f;
    for (int i = 0; i < LAT; i++)
        acc = __fadd_rn(acc, __fmul_rn(zr[i], zr[i]));
    g_zz[row] = acc;
}

// cc[c] = sequential ascending sum of fl(c_i * c_i)
__global__ void cc_kernel(const float* __restrict__ cb) {
    int c = blockIdx.x * 256 + threadIdx.x;
    if (c < KC) {
        const float* cr = cb + (size_t)c * LAT;
        float acc = 0.f;
        for (int i = 0; i < LAT; i++)
            acc = __fadd_rn(acc, __fmul_rn(cr[i], cr[i]));
        g_cc[c] = acc;
    }
}

// d = fl(fl(zz - m2) + cc); argmin with first-index tie-break
__global__ __launch_bounds__(256)
void argmin_kernel() {
    const int tid  = threadIdx.x;
    const int lane = tid & 31;
    const int wrp  = tid >> 5;
    const int row  = blockIdx.x * 8 + wrp;

    const float zz = g_zz[row];
    const float* zcr = g_zc + (size_t)row * KC;

    float best = 3.402823466e38f;
    int bi = KC;
    for (int j = 0; j < KC / 32; j++) {
        int c = j * 32 + lane;
        float d = __fadd_rn(__fsub_rn(zz, zcr[c]), g_cc[c]);
        if (d < best || (d == best && c < bi)) { best = d; bi = c; }
    }
    #pragma unroll
    for (int off = 16; off > 0; off >>= 1) {
        float ov = __shfl_down_sync(0xFFFFFFFFu, best, off);
        int   oi = __shfl_down_sync(0xFFFFFFFFu, bi,   off);
        if (ov < best || (ov == best && oi < bi)) { best = ov; bi = oi; }
    }
    if (lane == 0) g_idx[row] = bi;
}

// zq_st = fl(z + fl(zq - z)); vq partial = sum fl(zq - z)^2 per block
__global__ __launch_bounds__(256)
void zq_kernel(const float* __restrict__ z, const float* __restrict__ cb) {
    const int tid  = threadIdx.x;
    const int lane = tid & 31;
    const int wrp  = tid >> 5;
    const int row  = blockIdx.x * 8 + wrp;
    const int bi   = g_idx[row];

    float vs = 0.f;
    #pragma unroll
    for (int h = 0; h < 2; h++) {
        int i = h * 32 + lane;
        float zv = z[(size_t)row * LAT + i];
        float cv = cb[(size_t)bi * LAT + i];
        float df = __fsub_rn(cv, zv);
        g_zq[(size_t)row * LAT + i] = __fadd_rn(zv, df);
        vs = __fmaf_rn(df, df, vs);
    }
    #pragma unroll
    for (int off = 16; off > 0; off >>= 1)
        vs += __shfl_down_sync(0xFFFFFFFFu, vs, off);

    __shared__ float sv[8];
    if (lane == 0) sv[wrp] = vs;
    __syncthreads();
    if (tid == 0) {
        float s = 0.f;
        #pragma unroll
        for (int w = 0; w < 8; w++) s += sv[w];
        g_vpart[blockIdx.x] = s;
    }
}

// ================================================================
// PART 2: fast tf32x3 decoder (tolerance-checked path)
// ================================================================
__device__ __forceinline__ void mma_tf32(float* c, const uint32_t* a, const uint32_t* b) {
    asm volatile(
        "mma.sync.aligned.m16n8k8.row.col.f32.tf32.tf32.f32 "
        "{%0,%1,%2,%3},{%4,%5,%6,%7},{%8,%9},{%0,%1,%2,%3};\n"
        : "+f"(c[0]), "+f"(c[1]), "+f"(c[2]), "+f"(c[3])
        : "r"(a[0]), "r"(a[1]), "r"(a[2]), "r"(a[3]),
          "r"(b[0]), "r"(b[1]));
}
__device__ __forceinline__ float tf32_hi(float x) {
    return __uint_as_float(__float_as_uint(x) & 0xFFFFE000u);
}

constexpr int BM = 128, BN = 64, BK = 16;
constexpr int SA = 20, SB = 72;

template<bool RELU, bool FINAL>
__global__ __launch_bounds__(256)
void gemm_x3(const float* __restrict__ A, const float* __restrict__ W,
             const float* __restrict__ bias, float* __restrict__ C,
             int M, int N, int K,
             const float* __restrict__ xref, float* __restrict__ part)
{
    __shared__ float As[2][BM * SA];
    __shared__ float Bs[2][BK * SB];

    const int tid  = threadIdx.x;
    const int lane = tid & 31;
    const int warp = tid >> 5;
    const int gid  = lane >> 2;
    const int tig  = lane & 3;
    const int wm   = warp & 3;
    const int wn   = warp >> 2;
    const int rowBlk = blockIdx.y * BM;
    const int colBlk = blockIdx.x * BN;

    float acc[2][4][4];
    #pragma unroll
    for (int i = 0; i < 2; i++)
        #pragma unroll
        for (int j = 0; j < 4; j++)
            #pragma unroll
            for (int q = 0; q < 4; q++) acc[i][j][q] = 0.f;

    for (int k0 = 0; k0 < K; k0 += BK) {
        #pragma unroll
        for (int i = 0; i < 2; i++) {
            int idx = tid + i * 256;
            int r  = idx >> 2;
            int kc = (idx & 3) * 4;
            float4 v = *(const float4*)(A + (size_t)(rowBlk + r) * K + (k0 + kc));
            float4 h, l;
            h.x = tf32_hi(v.x); h.y = tf32_hi(v.y); h.z = tf32_hi(v.z); h.w = tf32_hi(v.w);
            l.x = v.x - h.x;    l.y = v.y - h.y;    l.z = v.z - h.z;    l.w = v.w - h.w;
            *(float4*)&As[0][r * SA + kc] = h;
            *(float4*)&As[1][r * SA + kc] = l;
        }
        {
            int kr = tid >> 4;
            int nc = (tid & 15) * 4;
            float4 v = *(const float4*)(W + (size_t)(k0 + kr) * N + (colBlk + nc));
            float4 h, l;
            h.x = tf32_hi(v.x); h.y = tf32_hi(v.y); h.z = tf32_hi(v.z); h.w = tf32_hi(v.w);
            l.x = v.x - h.x;    l.y = v.y - h.y;    l.z = v.z - h.z;    l.w = v.w - h.w;
            *(float4*)&Bs[0][kr * SB + nc] = h;
            *(float4*)&Bs[1][kr * SB + nc] = l;
        }
        __syncthreads();

        #pragma unroll
        for (int ks = 0; ks < BK / 8; ks++) {
            uint32_t a[2][4], b[4][2], al[2][4], bl[4][2];
            #pragma unroll
            for (int mt = 0; mt < 2; mt++) {
                int rb = wm * 32 + mt * 16 + gid;
                int cc2 = ks * 8 + tig;
                a[mt][0]  = __float_as_uint(As[0][rb * SA + cc2]);
                a[mt][1]  = __float_as_uint(As[0][(rb + 8) * SA + cc2]);
                a[mt][2]  = __float_as_uint(As[0][rb * SA + cc2 + 4]);
                a[mt][3]  = __float_as_uint(As[0][(rb + 8) * SA + cc2 + 4]);
                al[mt][0] = __float_as_uint(As[1][rb * SA + cc2]);
                al[mt][1] = __float_as_uint(As[1][(rb + 8) * SA + cc2]);
                al[mt][2] = __float_as_uint(As[1][rb * SA + cc2 + 4]);
                al[mt][3] = __float_as_uint(As[1][(rb + 8) * SA + cc2 + 4]);
            }
            #pragma unroll
            for (int nt = 0; nt < 4; nt++) {
                int nn = wn * 32 + nt * 8 + gid;
                int kk = ks * 8 + tig;
                b[nt][0]  = __float_as_uint(Bs[0][kk * SB + nn]);
                b[nt][1]  = __float_as_uint(Bs[0][(kk + 4) * SB + nn]);
                bl[nt][0] = __float_as_uint(Bs[1][kk * SB + nn]);
                bl[nt][1] = __float_as_uint(Bs[1][(kk + 4) * SB + nn]);
            }
            #pragma unroll
            for (int mt = 0; mt < 2; mt++)
                #pragma unroll
                for (int nt = 0; nt < 4; nt++) {
                    mma_tf32(acc[mt][nt], a[mt], b[nt]);
                    mma_tf32(acc[mt][nt], al[mt], b[nt]);
                    mma_tf32(acc[mt][nt], a[mt], bl[nt]);
                }
        }
        __syncthreads();
    }

    float lsum = 0.f;
    #pragma unroll
    for (int mt = 0; mt < 2; mt++) {
        #pragma unroll
        for (int nt = 0; nt < 4; nt++) {
            int col = colBlk + wn * 32 + nt * 8 + tig * 2;
            float b0 = bias[col], b1 = bias[col + 1];
            #pragma unroll
            for (int h = 0; h < 2; h++) {
                int row = rowBlk + wm * 32 + mt * 16 + gid + h * 8;
                float v0 = acc[mt][nt][h * 2 + 0] + b0;
                float v1 = acc[mt][nt][h * 2 + 1] + b1;
                if (RELU) { v0 = fmaxf(v0, 0.f); v1 = fmaxf(v1, 0.f); }
                *(float2*)(C + (size_t)row * N + col) = make_float2(v0, v1);
                if (FINAL) {
                    float x0 = xref[(size_t)row * N + col];
                    float x1 = xref[(size_t)row * N + col + 1];
                    float d0 = v0 - x0, d1 = v1 - x1;
                    lsum += d0 * d0 + d1 * d1;
                }
            }
        }
    }
    if (FINAL) {
        __shared__ float red[256];
        red[tid] = lsum;
        __syncthreads();
        #pragma unroll
        for (int s = 128; s > 0; s >>= 1) {
            if (tid < s) red[tid] += red[tid + s];
            __syncthreads();
        }
        if (tid == 0) part[blockIdx.y * gridDim.x + blockIdx.x] = red[0];
    }
}

// ---------------- tail outputs ----------------
__global__ void idxf_kernel(float* __restrict__ out) {
    int i = blockIdx.x * 256 + threadIdx.x;
    if (i < BATCH) out[i] = (float)g_idx[i];
}

__global__ __launch_bounds__(256)
void finalize_kernel(float* __restrict__ out) {
    __shared__ double sd[256];
    int tid = threadIdx.x;
    double s = 0.0;
    for (int i = tid; i < 8192; i += 256) s += (double)g_rpart[i];
    sd[tid] = s;
    __syncthreads();
    for (int st = 128; st > 0; st >>= 1) {
        if (tid < st) sd[tid] += sd[tid + st];
        __syncthreads();
    }
    double recon_sum = sd[0];
    __syncthreads();
    s = 0.0;
    for (int i = tid; i < 2048; i += 256) s += (double)g_vpart[i];
    sd[tid] = s;
    __syncthreads();
    for (int st = 128; st > 0; st >>= 1) {
        if (tid < st) sd[tid] += sd[tid + st];
        __syncthreads();
    }
    if (tid == 0) {
        double recon = recon_sum / ((double)BATCH * (double)NPTS);
        double vq    = 1.25 * sd[0] / ((double)BATCH * (double)LAT);
        out[0] = (float)(recon + vq);
        out[1] = (float)recon;
        out[2] = (float)vq;
    }
}

// ---------------- launch ----------------
extern "C" void kernel_launch(void* const* d_in, const int* in_sizes, int n_in,
                              void* d_out, int out_size)
{
    const float* x   = (const float*)d_in[0];
    const float* ew1 = (const float*)d_in[1];
    const float* eb1 = (const float*)d_in[2];
    const float* ew2 = (const float*)d_in[3];
    const float* eb2 = (const float*)d_in[4];
    const float* ew3 = (const float*)d_in[5];
    const float* eb3 = (const float*)d_in[6];
    const float* cb  = (const float*)d_in[7];
    const float* dw1 = (const float*)d_in[8];
    const float* db1 = (const float*)d_in[9];
    const float* dw2 = (const float*)d_in[10];
    const float* db2 = (const float*)d_in[11];
    const float* dw3 = (const float*)d_in[12];
    const float* db3 = (const float*)d_in[13];
    float* out = (float*)d_out;

    float *h1, *h2, *z, *zq, *zc, *cbT, *rpart;
    cudaGetSymbolAddress((void**)&h1, g_h1);
    cudaGetSymbolAddress((void**)&h2, g_h2);
    cudaGetSymbolAddress((void**)&z,  g_z);
    cudaGetSymbolAddress((void**)&zq, g_zq);
    cudaGetSymbolAddress((void**)&zc, g_zc);
    cudaGetSymbolAddress((void**)&cbT, g_cbT);
    cudaGetSymbolAddress((void**)&rpart, g_rpart);

    dim3 blk(256);

    // ---- encoder: bit-exact sequential-k fp32 (Eigen-order), FFMA2-packed ----
    seqk_gemm2<true,  true,  false><<<dim3(512 / 128,  BATCH / 128), blk>>>(x,  ew1, eb1, h1, BATCH, 512, NPTS);
    seqk_gemm2<true,  true,  false><<<dim3(256 / 128,  BATCH / 128), blk>>>(h1, ew2, eb2, h2, BATCH, 256, 512);
    seqk_gemm <false, true,  false><<<dim3(64 / 64,    BATCH / 64),  blk>>>(h2, ew3, eb3, z,  BATCH, 64,  256);

    // ---- VQ: bit-exact d + first-index argmin ----
    cbT_kernel<<<(KC * LAT) / 256, blk>>>(cb);
    cc_kernel<<<KC / 256, blk>>>(cb);
    zz_kernel<<<BATCH / 256, blk>>>(z);
    seqk_gemm2<false, false, true ><<<dim3(KC / 128, BATCH / 128), blk>>>(z, cbT, nullptr, zc, BATCH, KC, LAT);
    argmin_kernel<<<BATCH / 8, blk>>>();
    zq_kernel<<<BATCH / 8, blk>>>(z, cb);

    // ---- decoder: fast tf32x3 (tolerance path) ----
    gemm_x3<true,  false><<<dim3(256 / BN,  BATCH / BM), blk>>>(zq, dw1, db1, h2, BATCH, 256,  LAT, nullptr, nullptr);
    gemm_x3<true,  false><<<dim3(512 / BN,  BATCH / BM), blk>>>(h2, dw2, db2, h1, BATCH, 512,  256, nullptr, nullptr);
    gemm_x3<false, true ><<<dim3(NPTS / BN, BATCH / BM), blk>>>(h1, dw3, db3, out, BATCH, NPTS, 512, x, rpart);

    // ---- tail outputs ----
    idxf_kernel<<<BATCH / 256, blk>>>(out + (size_t)BATCH * NPTS);
    finalize_kernel<<<1, blk>>>(out + (size_t)BATCH * NPTS + BATCH);
}